// round 2
// baseline (speedup 1.0000x reference)
#include <cuda_runtime.h>
#include <cstdint>

// out[b][o][i][l] = white_table[o][i][ x[b][i][o][l] ]
// B=8, O=I=64, L=2048. L-axis contiguous on both sides -> fully coalesced.
// One block per (o,i) pair: load 1KB LUT to smem once, stream all 8 batches vec4.

#define B_DIM 8
#define CH 64
#define L_DIM 2048
#define THREADS 256

__global__ __launch_bounds__(THREADS) void white_transpose_kernel(
    const int* __restrict__ x,
    const float* __restrict__ table,
    float* __restrict__ out)
{
    const int idx = blockIdx.x;          // 0..4095
    const int i = idx & (CH - 1);
    const int o = idx >> 6;

    __shared__ float lut[256];
    // LUT for (o, i): table[(o*64 + i)*256 + k]
    const float* t = table + ((o * CH + i) << 8);
    if (threadIdx.x < 256) lut[threadIdx.x] = t[threadIdx.x];
    __syncthreads();

    // per-batch strides (in elements): input advances by 64*64*2048, same for output
    const size_t bstride = (size_t)CH * CH * L_DIM;
    const int* xrow = x + ((size_t)(i * CH + o) * L_DIM);
    float* orow = out + ((size_t)(o * CH + i) * L_DIM);

    #pragma unroll
    for (int b = 0; b < B_DIM; b++) {
        const int4* __restrict__ xin =
            reinterpret_cast<const int4*>(xrow + b * bstride);
        float4* __restrict__ op =
            reinterpret_cast<float4*>(orow + b * bstride);

        // 2048 elems = 512 int4; 256 threads -> 2 vec iterations
        #pragma unroll
        for (int v = 0; v < (L_DIM / 4) / THREADS; v++) {
            const int vi = v * THREADS + threadIdx.x;
            int4 xi = xin[vi];
            float4 r;
            r.x = lut[xi.x];
            r.y = lut[xi.y];
            r.z = lut[xi.z];
            r.w = lut[xi.w];
            op[vi] = r;
        }
    }
}

extern "C" void kernel_launch(void* const* d_in, const int* in_sizes, int n_in,
                              void* d_out, int out_size)
{
    const int* x = (const int*)d_in[0];          // [8, 64, 64, 2048] int32
    const float* table = (const float*)d_in[1];  // [64, 64, 256] float32
    float* out = (float*)d_out;                  // [8, 64, 64, 2048] float32

    const int grid = CH * CH;  // 4096 blocks, one per (o,i)
    white_transpose_kernel<<<grid, THREADS>>>(x, table, out);
}